// round 16
// baseline (speedup 1.0000x reference)
#include <cuda_runtime.h>
#include <cuda_bf16.h>
#include <cstdint>
#include <cstring>

// ---------------- constants ----------------
constexpr int NP = 8192;
constexpr int PER_BLK_W = 737280;
constexpr size_t PER_BLK_U = 5242880;      // Winograd weights bytes per flow block
constexpr size_t MP_PER_BLK = 147456;

// ---------------- device scratch ----------------
__device__ char g_wpu[32 * PER_BLK_U];     // Winograd conv weights (frag chunks, hi/lo)
__device__ char g_mpc[32 * MP_PER_BLK];    // mixing weights (frag chunks, hi/lo)
__device__ float g_Xa[NP * 192], g_Xb[NP * 192];
__device__ __nv_bfloat16 g_XaH[NP * 192], g_XaL[NP * 192];
__device__ __nv_bfloat16 g_XbH[NP * 192], g_XbL[NP * 192];
__device__ float g_T1[NP * 128], g_T2[NP * 128];

// ---------------- helpers ----------------
__device__ __forceinline__ uint32_t smem_u32(const void* p) {
    uint32_t a;
    asm("{ .reg .u64 t; cvta.to.shared.u64 t, %1; cvt.u32.u64 %0, t; }" : "=r"(a) : "l"(p));
    return a;
}
__device__ __forceinline__ unsigned short f2bf(float v) {
    __nv_bfloat16 b = __float2bfloat16(v);
    unsigned short u; memcpy(&u, &b, 2);
    return u;
}
__device__ __forceinline__ float bf2f(unsigned short u) {
    __nv_bfloat16 b; memcpy(&b, &u, 2);
    return __bfloat162float(b);
}
__device__ __forceinline__ void ldm4(uint32_t* r, uint32_t addr) {
    asm volatile("ldmatrix.sync.aligned.m8n8.x4.shared.b16 {%0,%1,%2,%3}, [%4];"
        : "=r"(r[0]), "=r"(r[1]), "=r"(r[2]), "=r"(r[3]) : "r"(addr));
}
__device__ __forceinline__ void mma16816(float* d, const uint32_t* a, uint32_t b0, uint32_t b1) {
    asm volatile("mma.sync.aligned.m16n8k16.row.col.f32.bf16.bf16.f32 "
        "{%0,%1,%2,%3},{%4,%5,%6,%7},{%8,%9},{%0,%1,%2,%3};"
        : "+f"(d[0]), "+f"(d[1]), "+f"(d[2]), "+f"(d[3])
        : "r"(a[0]), "r"(a[1]), "r"(a[2]), "r"(a[3]), "r"(b0), "r"(b1));
}
__device__ __forceinline__ void cpa16(uint32_t dst, const void* src, uint32_t srcsz) {
    asm volatile("cp.async.cg.shared.global [%0], [%1], 16, %2;"
        :: "r"(dst), "l"(src), "r"(srcsz) : "memory");
}
#define CP_COMMIT() asm volatile("cp.async.commit_group;" ::: "memory")
#define CP_WAIT0()  asm volatile("cp.async.wait_group 0;" ::: "memory")

// ---------------- Winograd weight prepack ----------------
// U = G g G^T per (o,c); 16 coordinates. Stored per conv as fragment chunks:
// chunk key ((xi*KST + k16)*TILES + n8tile) * 512B; hi plane then lo plane;
// within plane: lane=(o&7)*4+((kk&7)>>1) byte=((kk>>3)&1)*4+(kk&1)*2, kk=c&15.
__global__ void k_wu(const float* __restrict__ wf) {
    int idx = blockIdx.x * 256 + threadIdx.x;
    if (idx >= 32 * 81920) return;
    int blk = idx / 81920;
    int r = idx - blk * 81920;
    const int cum[7] = {0, 12288, 28672, 40960, 53248, 69632, 81920};
    const int wst[6] = {0, 110592, 258048, 368640, 479232, 626688};
    const size_t pu[6] = {0, 786432, 1835008, 2621440, 3407872, 4456448};
    int j = 0;
#pragma unroll
    for (int t = 1; t < 6; t++) if (r >= cum[t]) j = t;
    int rr = r - cum[j];
    int oc = ((j % 3) == 2) ? 96 : 128;
    int ic = ((j % 3) == 0) ? 96 : 128;
    int o = rr / ic, c = rr - o * ic;
    const float* g = wf + (size_t)blk * PER_BLK_W + wst[j] + (size_t)(o * ic + c) * 9;
    float T[4][3];
#pragma unroll
    for (int jx = 0; jx < 3; jx++) {
        float g0 = g[jx], g1 = g[3 + jx], g2 = g[6 + jx];
        T[0][jx] = g0;
        T[1][jx] = (g0 + g1 + g2) * 0.5f;
        T[2][jx] = (g0 - g1 + g2) * 0.5f;
        T[3][jx] = g2;
    }
    int kst = ic >> 4, tiles = oc >> 3, kk = c & 15;
    size_t fragoff = (size_t)((o & 7) * 4 + ((kk & 7) >> 1)) * 8
                   + ((kk >> 3) & 1) * 4 + (kk & 1) * 2;
    size_t base = (size_t)blk * PER_BLK_U + pu[j];
#pragma unroll
    for (int a = 0; a < 4; a++) {
        float u0 = T[a][0], u1 = T[a][1], u2 = T[a][2];
        float U[4] = {u0, (u0 + u1 + u2) * 0.5f, (u0 - u1 + u2) * 0.5f, u2};
#pragma unroll
        for (int bb = 0; bb < 4; bb++) {
            int xi = a * 4 + bb;
            unsigned short hb = f2bf(U[bb]);
            unsigned short lb = f2bf(U[bb] - bf2f(hb));
            size_t ch = base + (size_t)((xi * kst + (c >> 4)) * tiles + (o >> 3)) * 512 + fragoff;
            *(unsigned short*)(g_wpu + ch) = hb;
            *(unsigned short*)(g_wpu + ch + 256) = lb;
        }
    }
}

// ---------------- mixing prepack: fragment-chunk layout ----------------
__global__ void k_mp(const float* __restrict__ m) {
    int idx = blockIdx.x * 256 + threadIdx.x;
    if (idx >= 32 * 36864) return;
    int blk = idx / 36864;
    int r = idx - blk * 36864;
    int o = r / 192, c = r - o * 192;
    float v = m[idx];
    unsigned short hb = f2bf(v);
    unsigned short lb = f2bf(v - bf2f(hb));
    int kk = c & 15;
    size_t chunk = (size_t)((c >> 4) * 24 + (o >> 3)) * 512;
    size_t e = chunk + (size_t)((o & 7) * 4 + ((kk & 7) >> 1)) * 8
             + ((kk >> 3) & 1) * 4 + (kk & 1) * 2;
    size_t base = (size_t)blk * MP_PER_BLK;
    *(unsigned short*)(g_mpc + base + e) = hb;
    *(unsigned short*)(g_mpc + base + 256 + e) = lb;
}

// ---------------- normalize + permute + space_to_depth -> NHWC fp32 ----------------
__global__ void k_pre(const float* __restrict__ x, const float* __restrict__ mu,
                      const float* __restrict__ sigma, const int* __restrict__ perm,
                      float* __restrict__ Xo) {
    int idx = blockIdx.x * 256 + threadIdx.x;
    if (idx >= NP * 192) return;
    int ch = idx % 192;
    int p = idx / 192;
    int w = p & 31, h = (p >> 5) & 31, b = p >> 10;
    int c = ch >> 6, r = ch & 63;
    int bi = r >> 3, bj = r & 7;
    int flat = (h * 8 + bi) * 256 + (w * 8 + bj);
    int src = perm[c * 65536 + flat];
    Xo[idx] = (x[(b * 3 + c) * 65536 + src] - mu[c]) / sigma[c];
}

// ---------------- final NHWC -> NCHW ----------------
__global__ void k_post(const float* __restrict__ X, float* __restrict__ out) {
    int idx = blockIdx.x * 256 + threadIdx.x;
    if (idx >= NP * 192) return;
    int w = idx & 31;
    int h = (idx >> 5) & 31;
    int ch = (idx >> 10) % 192;
    int b = idx / (192 * 1024);
    out[idx] = X[(((b * 32 + h) * 32 + w) * 192) + ch];
}

// ---------------- Winograd F(2x2,3x3) fused conv kernel ----------------
// CTA = one tile-row: 16 tiles of 2x2 outputs (image b, rows 2ty..2ty+1) x full OC.
// Loop xi=0..15: smem transform V[xi]=B^T d B (fp32 exact, hi/lo split) ->
// bf16x3 GEMM [16 x IC]x[IC x OC] (B streamed from gmem fragment chunks) ->
// M[xi] to smem. Epilogue: y = A^T M A + bias/relu/residual (+ hi/lo split).
template <int IC, int OC, int NW, bool RELU, bool ADDIN, bool WRHL>
__global__ __launch_bounds__(NW * 32, 1) void k_win(
    const float* __restrict__ in, int in_stride,
    const char* __restrict__ wp,
    const float* __restrict__ bias,
    const float* __restrict__ addp,
    float* __restrict__ out, int out_stride,
    __nv_bfloat16* __restrict__ outH, __nv_bfloat16* __restrict__ outL)
{
    constexpr int THREADS = NW * 32;
    constexpr int KST = IC / 16;
    constexpr int TILES = OC / 8;
    constexpr int WN = OC / NW;           // warp N cols (16 or 8)
    constexpr int NT = WN / 8;            // n8 tiles per warp (2 or 1)
    constexpr int LDV = IC + 8;           // V row stride, b16 units
    constexpr int NSTEP = 16 * KST;
    constexpr int GSTRIDE = TILES * 512;
    constexpr int CH4 = IC / 4;           // 16B chunks per halo position

    extern __shared__ __align__(16) char sm[];
    float* halo = (float*)sm;                              // [136][IC] fp32
    unsigned short* Vh = (unsigned short*)(sm + 136 * IC * 4);
    unsigned short* Vl = Vh + 16 * LDV;
    float* M = (float*)(sm + 136 * IC * 4 + 4 * 16 * LDV); // [16][16][OC] fp32

    const int tid = threadIdx.x;
    const int wid = tid >> 5, lane = tid & 31;
    const int wn = wid;
    const int t = blockIdx.x;
    const int b = t >> 4;
    const int ty = t & 15;

    // ---- halo load (once): image rows 2ty-1..2ty+2, cols -1..32 ----
    for (int i = tid; i < 136 * CH4; i += THREADS) {
        int pos = i / CH4, ck = i - pos * CH4;
        int hr = pos / 34, hc = pos - hr * 34;
        int hh = 2 * ty - 1 + hr, ww = hc - 1;
        bool ok = (hh >= 0) && (hh < 32) && (ww >= 0) && (ww < 32);
        const float* src = ok ? (in + (size_t)((b * 32 + hh) * 32 + ww) * in_stride + ck * 4) : in;
        cpa16(smem_u32(halo + pos * IC + ck * 4), src, ok ? 16u : 0u);
    }
    CP_COMMIT();

    // B stream (linear in gs = xi*KST + ks)
    const char* bptr = wp + (size_t)(wn * NT) * 512 + (size_t)lane * 8;
    uint2 rbh[2][NT], rbl[2][NT];
#pragma unroll
    for (int nt = 0; nt < NT; nt++) {
        rbh[0][nt] = *(const uint2*)(bptr + nt * 512);
        rbl[0][nt] = *(const uint2*)(bptr + nt * 512 + 256);
    }
    const char* bpre = bptr + GSTRIDE;

    CP_WAIT0();
    __syncthreads();

    const uint32_t sVh = smem_u32(Vh), sVl = smem_u32(Vl);
    const uint32_t apix = (uint32_t)((lane & 15) * (LDV * 2)) + ((lane >> 4) * 16);
    uint32_t fah[2][4], fal[2][4];

    // B^T sign tables: e[a] = vs0[a]*d[vi0[a]] + vs1[a]*d[vi1[a]]
    const int   vi0[4] = {0, 1, 1, 1};
    const float vs0[4] = {1.f, 1.f, -1.f, 1.f};
    const int   vi1[4] = {2, 2, 2, 3};
    const float vs1[4] = {-1.f, 1.f, 1.f, -1.f};

    int gs = 0;
    for (int xi = 0; xi < 16; xi++) {
        const int a = xi >> 2, bb_ = xi & 3;
        const int r0 = vi0[a], r1 = vi1[a];
        const float sr0 = vs0[a], sr1 = vs1[a];
        const int c0 = vi0[bb_], c1 = vi1[bb_];
        const float sc0 = vs0[bb_], sc1 = vs1[bb_];

        // ---- transform V[xi] (fp32 sums, then hi/lo split) ----
        for (int e = tid; e < 16 * (IC / 2); e += THREADS) {
            int tt = e / (IC / 2);
            int cp = e - tt * (IC / 2);
            int c = cp * 2;
            const float* dbase = halo + (2 * tt) * IC + c;
            float2 d00 = *(const float2*)(dbase + (r0 * 34 + c0) * IC);
            float2 d01 = *(const float2*)(dbase + (r0 * 34 + c1) * IC);
            float2 d10 = *(const float2*)(dbase + (r1 * 34 + c0) * IC);
            float2 d11 = *(const float2*)(dbase + (r1 * 34 + c1) * IC);
            float vx = sr0 * (sc0 * d00.x + sc1 * d01.x) + sr1 * (sc0 * d10.x + sc1 * d11.x);
            float vy = sr0 * (sc0 * d00.y + sc1 * d01.y) + sr1 * (sc0 * d10.y + sc1 * d11.y);
            __nv_bfloat162 h = __float22bfloat162_rn(make_float2(vx, vy));
            float2 hf = __bfloat1622float2(h);
            __nv_bfloat162 l = __float22bfloat162_rn(make_float2(vx - hf.x, vy - hf.y));
            uint32_t uh, ul;
            memcpy(&uh, &h, 4); memcpy(&ul, &l, 4);
            *(uint32_t*)(Vh + tt * LDV + c) = uh;
            *(uint32_t*)(Vl + tt * LDV + c) = ul;
        }
        __syncthreads();

        // ---- GEMM [16 x IC] x [IC x OC] for this coordinate ----
        float accq[NT][4];
#pragma unroll
        for (int nt = 0; nt < NT; nt++)
#pragma unroll
            for (int q = 0; q < 4; q++) accq[nt][q] = 0.f;

        ldm4(fah[0], sVh + apix);
        ldm4(fal[0], sVl + apix);
#pragma unroll
        for (int ks = 0; ks < KST; ks++) {
            const int pb = ks & 1;            // == gs&1 since KST even
            if (ks + 1 < KST) {
                ldm4(fah[pb ^ 1], sVh + apix + (uint32_t)(ks + 1) * 32);
                ldm4(fal[pb ^ 1], sVl + apix + (uint32_t)(ks + 1) * 32);
            }
            {   // B prefetch for gs+1 into slot pb^1
                const char* bp = (gs + 1 < NSTEP) ? bpre : bptr;
#pragma unroll
                for (int nt = 0; nt < NT; nt++) {
                    rbh[pb ^ 1][nt] = *(const uint2*)(bp + nt * 512);
                    rbl[pb ^ 1][nt] = *(const uint2*)(bp + nt * 512 + 256);
                }
            }
#pragma unroll
            for (int nt = 0; nt < NT; nt++)
                mma16816(accq[nt], fah[pb], rbh[pb][nt].x, rbh[pb][nt].y);
#pragma unroll
            for (int nt = 0; nt < NT; nt++)
                mma16816(accq[nt], fah[pb], rbl[pb][nt].x, rbl[pb][nt].y);
#pragma unroll
            for (int nt = 0; nt < NT; nt++)
                mma16816(accq[nt], fal[pb], rbh[pb][nt].x, rbh[pb][nt].y);
            bpre += GSTRIDE;
            gs++;
        }

        // ---- write M[xi] to smem ----
        {
            const int mr = lane >> 2;
            const int mc = (lane & 3) * 2;
#pragma unroll
            for (int nt = 0; nt < NT; nt++) {
                const int col = wn * WN + nt * 8 + mc;
                *(float2*)(M + (xi * 16 + mr) * OC + col) = make_float2(accq[nt][0], accq[nt][1]);
                *(float2*)(M + (xi * 16 + mr + 8) * OC + col) = make_float2(accq[nt][2], accq[nt][3]);
            }
        }
        __syncthreads();
    }

    // ---- epilogue: y = A^T M A, bias/relu/residual, stores ----
    for (int e = tid; e < 16 * 4 * (OC / 2); e += THREADS) {
        int tt = e / (4 * (OC / 2));
        int r2 = e - tt * 4 * (OC / 2);
        int oyx = r2 / (OC / 2);
        int cp = r2 - oyx * (OC / 2);
        int oy = oyx >> 1, ox = oyx & 1;
        int col = cp * 2;
        float2 mv[16];
#pragma unroll
        for (int k = 0; k < 16; k++)
            mv[k] = *(const float2*)(M + (k * 16 + tt) * OC + col);
        // column combine (over b) with A^T[ox]
        float2 n[4];
#pragma unroll
        for (int aa = 0; aa < 4; aa++) {
            float2 m0 = mv[aa * 4 + 0], m1 = mv[aa * 4 + 1];
            float2 m2 = mv[aa * 4 + 2], m3 = mv[aa * 4 + 3];
            if (ox == 0) { n[aa].x = m0.x + m1.x + m2.x; n[aa].y = m0.y + m1.y + m2.y; }
            else         { n[aa].x = m1.x - m2.x - m3.x; n[aa].y = m1.y - m2.y - m3.y; }
        }
        float v0, v1;
        if (oy == 0) { v0 = n[0].x + n[1].x + n[2].x; v1 = n[0].y + n[1].y + n[2].y; }
        else         { v0 = n[1].x - n[2].x - n[3].x; v1 = n[1].y - n[2].y - n[3].y; }
        v0 += bias[col]; v1 += bias[col + 1];
        if (RELU) { v0 = fmaxf(v0, 0.f); v1 = fmaxf(v1, 0.f); }
        const int p = b * 1024 + (2 * ty + oy) * 32 + (2 * tt + ox);
        if (ADDIN) {
            float2 av = *(const float2*)(addp + (size_t)p * out_stride + col);
            v0 += av.x; v1 += av.y;
        }
        *(float2*)(out + (size_t)p * out_stride + col) = make_float2(v0, v1);
        if (WRHL) {
            __nv_bfloat162 h = __float22bfloat162_rn(make_float2(v0, v1));
            float2 hf = __bfloat1622float2(h);
            __nv_bfloat162 l = __float22bfloat162_rn(make_float2(v0 - hf.x, v1 - hf.y));
            *(__nv_bfloat162*)(outH + (size_t)p * out_stride + col) = h;
            *(__nv_bfloat162*)(outL + (size_t)p * out_stride + col) = l;
        }
    }
}

// ---------------- mixing GEMM (R15, proven): 512 thr, 16 warps 4Mx4N ----------------
template <int IC, int OC>
__global__ __launch_bounds__(512, 1) void k_mma(
    const __nv_bfloat16* __restrict__ inH, const __nv_bfloat16* __restrict__ inL,
    int in_stride,
    const char* __restrict__ wp,
    float* __restrict__ out,
    __nv_bfloat16* __restrict__ outH, __nv_bfloat16* __restrict__ outL,
    int out_stride)
{
    constexpr int KST = IC / 16;
    constexpr int NSTEP = KST;
    constexpr int RD = 2;
    constexpr int CPRA = IC / 8;
    constexpr int LDCA = IC + 8;
    constexpr int LDCAb = LDCA * 2;
    constexpr int NT = OC / 32;
    constexpr int GSTRIDE = (OC / 8) * 512;

    extern __shared__ __align__(16) unsigned short smem[];
    unsigned short* Ah = smem;
    unsigned short* Al = Ah + 64 * LDCA;

    const int tid = threadIdx.x;
    const int wid = tid >> 5, lane = tid & 31;
    const int wm = wid & 3, wn = wid >> 2;
    const int p0 = blockIdx.x * 64;

    float acc[NT][4];
#pragma unroll
    for (int j = 0; j < NT; j++)
#pragma unroll
        for (int q = 0; q < 4; q++) acc[j][q] = 0.f;

    const uint32_t sAh = smem_u32(Ah), sAl = smem_u32(Al);
    uint32_t apix;
    {
        int p = wm * 16 + (lane & 15);
        apix = (uint32_t)(p * LDCAb) + ((lane >> 4) * 16);
    }

    for (int i = tid; i < 64 * CPRA; i += 512) {
        int pos = i / CPRA, ck = i - pos * CPRA;
        size_t off = (size_t)(p0 + pos) * in_stride + ck * 8;
        uint32_t d = (uint32_t)(pos * LDCA + ck * 8) * 2;
        cpa16(sAh + d, inH + off, 16);
        cpa16(sAl + d, inL + off, 16);
    }
    CP_COMMIT();

    const char* bwarp = wp + (size_t)(wn * NT) * 512 + (size_t)lane * 8;
    uint32_t fah[2][4], fal[2][4];
    uint2 rbh[RD][NT], rbl[RD][NT];

#pragma unroll
    for (int nt = 0; nt < NT; nt++) {
        rbh[0][nt] = *(const uint2*)(bwarp + nt * 512);
        rbl[0][nt] = *(const uint2*)(bwarp + nt * 512 + 256);
    }

    CP_WAIT0();
    __syncthreads();
    ldm4(fah[0], sAh + apix);
    ldm4(fal[0], sAl + apix);

    const char* bpre = bwarp + GSTRIDE;
#pragma unroll
    for (int ks = 0; ks < KST; ks++) {
        const int slot = ks % RD;
        const int wsl = (ks + RD - 1) % RD;
        const int pb = ks & 1;
        if (ks + 1 < KST) {
            ldm4(fah[pb ^ 1], sAh + apix + (uint32_t)(ks + 1) * 32);
            ldm4(fal[pb ^ 1], sAl + apix + (uint32_t)(ks + 1) * 32);
        }
        {
            const char* bp = (ks + RD - 1 < NSTEP) ? bpre : bwarp;
#pragma unroll
            for (int nt = 0; nt < NT; nt++) {
                rbh[wsl][nt] = *(const uint2*)(bp + nt * 512);
                rbl[wsl][nt] = *(const uint2*)(bp + nt * 512 + 256);
            }
        }
#pragma unroll
        for (int nt = 0; nt < NT; nt++)
            mma16816(acc[nt], fah[pb], rbh[slot][nt].x, rbh[slot][nt].y);
#pragma unroll
        for (int nt = 0; nt < NT; nt++)
            mma16816(acc[nt], fah[pb], rbl[slot][nt].x, rbl[slot][nt].y);
#pragma unroll
        for (int nt = 0; nt < NT; nt++)
            mma16816(acc[nt], fal[pb], rbh[slot][nt].x, rbh[slot][nt].y);
        bpre += GSTRIDE;
    }

    const int l4 = lane >> 2, l2 = (lane & 3) * 2;
#pragma unroll
    for (int nt = 0; nt < NT; nt++) {
        const int col = wn * (OC / 4) + nt * 8 + l2;
        const int pr = p0 + wm * 16 + l4;
        float* d = acc[nt];
        float v0 = d[0], v1 = d[1], v2 = d[2], v3 = d[3];
        *(float2*)(out + (size_t)pr * out_stride + col) = make_float2(v0, v1);
        *(float2*)(out + (size_t)(pr + 8) * out_stride + col) = make_float2(v2, v3);
        __nv_bfloat162 h01 = __float22bfloat162_rn(make_float2(v0, v1));
        __nv_bfloat162 h23 = __float22bfloat162_rn(make_float2(v2, v3));
        float2 f01 = __bfloat1622float2(h01);
        float2 f23 = __bfloat1622float2(h23);
        __nv_bfloat162 l01 = __float22bfloat162_rn(make_float2(v0 - f01.x, v1 - f01.y));
        __nv_bfloat162 l23 = __float22bfloat162_rn(make_float2(v2 - f23.x, v3 - f23.y));
        *(__nv_bfloat162*)(outH + (size_t)pr * out_stride + col) = h01;
        *(__nv_bfloat162*)(outH + (size_t)(pr + 8) * out_stride + col) = h23;
        *(__nv_bfloat162*)(outL + (size_t)pr * out_stride + col) = l01;
        *(__nv_bfloat162*)(outL + (size_t)(pr + 8) * out_stride + col) = l23;
    }
}

// ---------------- launch ----------------
extern "C" void kernel_launch(void* const* d_in, const int* in_sizes, int n_in,
                              void* d_out, int out_size) {
    const float* x     = (const float*)d_in[0];
    const float* mu    = (const float*)d_in[1];
    const float* sigma = (const float*)d_in[2];
    const float* wf    = (const float*)d_in[3];
    const float* bfl   = (const float*)d_in[4];
    const float* m     = (const float*)d_in[5];
    const int*   perm  = (const int*)d_in[6];
    float* out = (float*)d_out;

    char *wu, *mp;
    float *Xa, *Xb, *T1, *T2;
    __nv_bfloat16 *XaH, *XaL, *XbH, *XbL;
    cudaGetSymbolAddress((void**)&wu, g_wpu);
    cudaGetSymbolAddress((void**)&mp, g_mpc);
    cudaGetSymbolAddress((void**)&Xa, g_Xa);
    cudaGetSymbolAddress((void**)&Xb, g_Xb);
    cudaGetSymbolAddress((void**)&XaH, g_XaH);
    cudaGetSymbolAddress((void**)&XaL, g_XaL);
    cudaGetSymbolAddress((void**)&XbH, g_XbH);
    cudaGetSymbolAddress((void**)&XbL, g_XbL);
    cudaGetSymbolAddress((void**)&T1, g_T1);
    cudaGetSymbolAddress((void**)&T2, g_T2);

    // smem sizes: halo + V(hi,lo) + M
    const int SM_W1 = 136 * 96 * 4 + 4 * 16 * 104 + 16 * 16 * 128 * 4;   // 189,952
    const int SM_W2 = 136 * 128 * 4 + 4 * 16 * 136 + 16 * 16 * 128 * 4;  // 209,408
    const int SM_W3 = 136 * 128 * 4 + 4 * 16 * 136 + 16 * 16 * 96 * 4;   // 176,640
    const int SM_MX = 4 * (64 * 200);                                    // 51,200
    static bool attr_done = false;
    if (!attr_done) {
        cudaFuncSetAttribute(k_win<96, 128, 8, true, false, false>,  cudaFuncAttributeMaxDynamicSharedMemorySize, SM_W1);
        cudaFuncSetAttribute(k_win<128, 128, 8, true, false, false>, cudaFuncAttributeMaxDynamicSharedMemorySize, SM_W2);
        cudaFuncSetAttribute(k_win<128, 96, 12, false, true, true>,  cudaFuncAttributeMaxDynamicSharedMemorySize, SM_W3);
        cudaFuncSetAttribute(k_mma<192, 192>, cudaFuncAttributeMaxDynamicSharedMemorySize, SM_MX);
        attr_done = true;
    }

    k_wu<<<(32 * 81920 + 255) / 256, 256>>>(wf);
    k_mp<<<(32 * 36864 + 255) / 256, 256>>>(m);
    k_pre<<<(NP * 192 + 255) / 256, 256>>>(x, mu, sigma, perm, Xa);

    const size_t pu[6] = {0, 786432, 1835008, 2621440, 3407872, 4456448};
    const int bstart[6] = {0, 128, 256, 352, 480, 608};

    float* X = Xa;  __nv_bfloat16 *XH = XaH, *XL = XaL;
    float* Y = Xb;  __nv_bfloat16 *YH = XbH, *YL = XbL;
    for (int blk = 0; blk < 32; blk++) {
        const char* wb = wu + (size_t)blk * PER_BLK_U;
        const float* bb = bfl + blk * 704;
        // round 0: x1 += f0(x2)
        k_win<96, 128, 8, true, false, false><<<128, 256, SM_W1>>>(X + 96, 192, wb + pu[0], bb + bstart[0], nullptr, T1, 128, nullptr, nullptr);
        k_win<128, 128, 8, true, false, false><<<128, 256, SM_W2>>>(T1, 128, wb + pu[1], bb + bstart[1], nullptr, T2, 128, nullptr, nullptr);
        k_win<128, 96, 12, false, true, true><<<128, 384, SM_W3>>>(T2, 128, wb + pu[2], bb + bstart[2], X + 0, X + 0, 192, XH + 0, XL + 0);
        // round 1: x2 += f1(x1)
        k_win<96, 128, 8, true, false, false><<<128, 256, SM_W1>>>(X + 0, 192, wb + pu[3], bb + bstart[3], nullptr, T1, 128, nullptr, nullptr);
        k_win<128, 128, 8, true, false, false><<<128, 256, SM_W2>>>(T1, 128, wb + pu[4], bb + bstart[4], nullptr, T2, 128, nullptr, nullptr);
        k_win<128, 96, 12, false, true, true><<<128, 384, SM_W3>>>(T2, 128, wb + pu[5], bb + bstart[5], X + 96, X + 96, 192, XH + 96, XL + 96);
        // 1x1 mixing
        k_mma<192, 192><<<128, 512, SM_MX>>>(XH, XL, 192, mp + (size_t)blk * MP_PER_BLK, Y, YH, YL, 192);
        float* tf = X; X = Y; Y = tf;
        __nv_bfloat16* th = XH; XH = YH; YH = th;
        __nv_bfloat16* tl = XL; XL = YL; YL = tl;
    }

    k_post<<<(NP * 192 + 255) / 256, 256>>>(X, out);
}